// round 1
// baseline (speedup 1.0000x reference)
#include <cuda_runtime.h>

#define NA      102000
#define NFEAT   85
#define NC      80
#define KSEL    8192
#define CAP     16384
#define MAXDET  300
#define CONF    0.25f
#define IOUT    0.45f

// ---------------- device scratch (no allocs allowed) ----------------
__device__ unsigned int       g_keys[NA];
__device__ unsigned char      g_cls[NA];
__device__ unsigned int       g_hist1[65536];
__device__ unsigned int       g_hist2[65536];
__device__ int                g_B;
__device__ unsigned int       g_A;
__device__ unsigned int       g_T;
__device__ unsigned int       g_cnt;
__device__ unsigned long long g_surv[CAP];
__device__ float4             g_top_box[KSEL];
__device__ float              g_top_area[KSEL];
__device__ float              g_top_score[KSEL];
__device__ float              g_top_cls[KSEL];
__device__ unsigned int       g_top_idx[KSEL];

// ---------------- 0: zero scratch (graph replays must be idempotent) ----------------
__global__ void k_zero() {
    int i = blockIdx.x * blockDim.x + threadIdx.x;
    if (i < 65536) { g_hist1[i] = 0u; g_hist2[i] = 0u; }
    if (i == 0) g_cnt = 0u;
}

// ---------------- 1: decode scores/classes, coarse 16-bit histogram ----------------
__global__ void k_score(const float* __restrict__ preds, int n) {
    __shared__ float tile[128 * NFEAT];   // 43520 B (static, < 48KB)
    int base = blockIdx.x * 128;
    int cnt = n - base; if (cnt > 128) cnt = 128;
    if (cnt <= 0) return;
    int nel = cnt * NFEAT;
    const float* src = preds + (long long)base * NFEAT;
    for (int i = threadIdx.x; i < nel; i += 128) tile[i] = src[i];  // coalesced
    __syncthreads();
    int t = threadIdx.x;
    if (t < cnt) {
        const float* p = &tile[t * NFEAT];   // stride 85 (odd) -> conflict-free
        float obj = p[4];
        float best = -1.0f; int bi = 0;
        #pragma unroll 4
        for (int c = 0; c < NC; c++) {
            float v = __fmul_rn(p[5 + c], obj);   // exact XLA order: per-class mul then max
            if (v > best) { best = v; bi = c; }   // strict > = argmax first-tie
        }
        float score = (obj > CONF) ? best : 0.0f;
        unsigned key = __float_as_uint(score);    // score >= 0 -> bits monotone
        int a = base + t;
        g_keys[a] = key;
        g_cls[a]  = (unsigned char)bi;
        if (key) atomicAdd(&g_hist1[key >> 16], 1u);  // skip zeros (avoid hot bucket)
    }
}

// ---------------- 2: coarse threshold bucket ----------------
__global__ void k_findB() {
    __shared__ unsigned s_sum[256];
    int t = threadIdx.x;
    unsigned s = 0;
    for (int b = 0; b < 256; b++) s += g_hist1[t * 256 + b];
    s_sum[t] = s;
    __syncthreads();
    if (t == 0) {
        unsigned acc = 0; int B = -1; unsigned A = 0;
        for (int c = 255; c >= 0; c--) {
            if (acc + s_sum[c] >= (unsigned)KSEL) {
                for (int b = c * 256 + 255; b >= c * 256; b--) {
                    unsigned h = g_hist1[b];
                    if (acc + h >= (unsigned)KSEL) { B = b; A = acc; break; }
                    acc += h;
                }
                break;
            }
            acc += s_sum[c];
        }
        g_B = B; g_A = A;   // B = -1 -> fewer than KSEL positive scores
    }
}

// ---------------- 3: fine histogram within coarse bucket ----------------
__global__ void k_hist2(int n) {
    int a = blockIdx.x * blockDim.x + threadIdx.x;
    if (a < n) {
        int B = g_B;
        unsigned key = g_keys[a];
        if (B >= 0 && (int)(key >> 16) == B) atomicAdd(&g_hist2[key & 0xFFFFu], 1u);
    }
}

// ---------------- 4: exact fine threshold ----------------
__global__ void k_findF() {
    __shared__ unsigned s_sum[256];
    int t = threadIdx.x;
    int B = g_B;
    if (B < 0) { if (t == 0) g_T = 1u; return; }   // take all positives
    unsigned s = 0;
    for (int b = 0; b < 256; b++) s += g_hist2[t * 256 + b];
    s_sum[t] = s;
    __syncthreads();
    if (t == 0) {
        unsigned target = (unsigned)KSEL - g_A;
        unsigned acc = 0; unsigned T = ((unsigned)B << 16);
        bool done = false;
        for (int c = 255; c >= 0 && !done; c--) {
            if (acc + s_sum[c] >= target) {
                for (int b = c * 256 + 255; b >= c * 256; b--) {
                    unsigned h = g_hist2[b];
                    acc += h;
                    if (acc >= target) { T = ((unsigned)B << 16) | (unsigned)b; done = true; break; }
                }
            } else acc += s_sum[c];
        }
        g_T = T ? T : 1u;
    }
}

// ---------------- 5: compact survivors (warp-aggregated atomics) ----------------
__global__ void k_compact(int n) {
    int a = blockIdx.x * blockDim.x + threadIdx.x;
    unsigned T = g_T;
    bool pred = false; unsigned key = 0;
    if (a < n) { key = g_keys[a]; pred = (key >= T); }
    unsigned m = __ballot_sync(0xffffffffu, pred);
    if (m) {
        int lane = threadIdx.x & 31;
        int leader = __ffs(m) - 1;
        unsigned base = 0;
        if (lane == leader) base = atomicAdd(&g_cnt, (unsigned)__popc(m));
        base = __shfl_sync(0xffffffffu, base, leader);
        if (pred) {
            unsigned pos = base + (unsigned)__popc(m & ((1u << lane) - 1u));
            if (pos < CAP)
                g_surv[pos] = ((unsigned long long)key << 32) | (unsigned)(~a); // ~idx: lower idx sorts first
        }
    }
}

// ---------------- 6: single-block bitonic sort of 16384 keys, descending ----------------
__global__ void k_sort() {
    extern __shared__ unsigned long long s[];
    int tid = threadIdx.x;
    unsigned C = g_cnt; if (C > CAP) C = CAP;
    for (int t = tid; t < CAP; t += 1024) s[t] = (t < (int)C) ? g_surv[t] : 0ULL;
    __syncthreads();
    for (int k = 2; k <= CAP; k <<= 1) {
        for (int j = k >> 1; j > 0; j >>= 1) {
            for (int t = tid; t < CAP / 2; t += 1024) {
                int i = (t & (j - 1)) | ((t & ~(j - 1)) << 1);
                int p = i | j;
                unsigned long long a = s[i], b = s[p];
                bool up = ((i & k) == 0);
                if ((a < b) == up) { s[i] = b; s[p] = a; }
            }
            __syncthreads();
        }
    }
    for (int t = tid; t < KSEL; t += 1024) {
        unsigned long long v = s[t];
        g_top_score[t] = __uint_as_float((unsigned)(v >> 32));
        g_top_idx[t]   = ~(unsigned)(v & 0xFFFFFFFFu);
    }
}

// ---------------- 7: gather boxes/areas/classes for top-8192 ----------------
__global__ void k_gather(const float* __restrict__ preds) {
    int t = blockIdx.x * blockDim.x + threadIdx.x;
    if (t >= KSEL) return;
    unsigned idx = g_top_idx[t];
    float sc = g_top_score[t];
    float4 box = make_float4(0.f, 0.f, 0.f, 0.f);
    float area = 0.f, cls = 0.f;
    if (sc > 0.f && idx < (unsigned)NA) {
        const float* p = preds + (size_t)idx * NFEAT;
        float x = p[0], y = p[1], w = p[2], h = p[3];
        float hh = __fmul_rn(h, 0.5f), hw = __fmul_rn(w, 0.5f);
        box.x = __fsub_rn(y, hh);   // y1
        box.y = __fsub_rn(x, hw);   // x1
        box.z = __fadd_rn(y, hh);   // y2
        box.w = __fadd_rn(x, hw);   // x2
        area = __fmul_rn(__fsub_rn(box.z, box.x), __fsub_rn(box.w, box.y));
        cls = (float)g_cls[idx];
    }
    g_top_box[t] = box; g_top_area[t] = area; g_top_cls[t] = cls;
}

// ---------------- 8: greedy NMS, early-stop at 300 kept, write output ----------------
// dyn smem: boxes 131072 | areas 32768 | kept 1216 | sup 8192  = 173248 B
__global__ void k_nms(float* __restrict__ out) {
    extern __shared__ char sm[];
    float4* sb = (float4*)sm;
    float*  sa = (float*)(sm + 131072);
    int*    skept = (int*)(sm + 131072 + 32768);
    unsigned char* ssup = (unsigned char*)(sm + 131072 + 32768 + 1216);
    __shared__ int s_next, s_kept, s_cur;
    int tid = threadIdx.x;
    for (int t = tid; t < KSEL; t += 1024) {
        sb[t] = g_top_box[t];
        sa[t] = g_top_area[t];
        ssup[t] = (g_top_score[t] > 0.f) ? 0 : 1;   // invalid => can never be kept
    }
    if (tid == 0) { s_kept = 0; s_cur = 0; s_next = -1; }
    __syncthreads();
    for (;;) {
        if (tid < 32) {   // warp-0 ballot scan for next survivor
            int c = s_cur;
            int found = -1;
            while (c < KSEL) {
                int j = c + tid;
                bool ok = (j < KSEL) && (ssup[j] == 0);
                unsigned mm = __ballot_sync(0xffffffffu, ok);
                if (mm) { found = c + __ffs(mm) - 1; break; }
                c += 32;
            }
            if (tid == 0) {
                if (found >= 0 && s_kept < MAXDET) {
                    skept[s_kept] = found; s_kept = s_kept + 1;
                    s_cur = found + 1; s_next = found;
                } else s_next = -1;
            }
        }
        __syncthreads();
        int i = s_next;
        if (i < 0) break;
        float4 bi = sb[i]; float ai = sa[i];
        for (int j = i + 1 + tid; j < KSEL; j += 1024) {
            if (!ssup[j]) {
                float4 bj = sb[j];
                float ty = fmaxf(bi.x, bj.x);
                float tx = fmaxf(bi.y, bj.y);
                float by = fminf(bi.z, bj.z);
                float bx = fminf(bi.w, bj.w);
                float ih = fmaxf(__fsub_rn(by, ty), 0.f);
                float iw = fmaxf(__fsub_rn(bx, tx), 0.f);
                float inter = __fmul_rn(ih, iw);
                float uni = __fsub_rn(__fadd_rn(ai, sa[j]), inter);
                float iou = __fdiv_rn(inter, __fadd_rn(uni, 1e-9f));
                if (iou > IOUT) ssup[j] = 1;
            }
        }
        __syncthreads();
    }
    // outputs: boxes [0,1200) | classes [1200,1500) | scores [1500,1800)
    int m = s_kept;
    for (int t = tid; t < MAXDET; t += 1024) {
        float4 b = make_float4(0.f, 0.f, 0.f, 0.f); float c = 0.f, s = 0.f;
        if (t < m) {
            int ki = skept[t];
            b = sb[ki];
            c = g_top_cls[ki];
            s = g_top_score[ki];
        }
        out[4 * t + 0] = b.x; out[4 * t + 1] = b.y;
        out[4 * t + 2] = b.z; out[4 * t + 3] = b.w;
        out[1200 + t] = c;
        out[1500 + t] = s;
    }
}

// ---------------- launch ----------------
extern "C" void kernel_launch(void* const* d_in, const int* in_sizes, int n_in,
                              void* d_out, int out_size) {
    const float* preds = (const float*)d_in[0];
    float* out = (float*)d_out;
    int n = in_sizes[0] / NFEAT;
    if (n > NA) n = NA;

    cudaFuncSetAttribute(k_sort, cudaFuncAttributeMaxDynamicSharedMemorySize, CAP * 8);
    cudaFuncSetAttribute(k_nms,  cudaFuncAttributeMaxDynamicSharedMemorySize, 173248);

    k_zero<<<256, 256>>>();
    k_score<<<(n + 127) / 128, 128>>>(preds, n);
    k_findB<<<1, 256>>>();
    k_hist2<<<(n + 255) / 256, 256>>>(n);
    k_findF<<<1, 256>>>();
    k_compact<<<(n + 255) / 256, 256>>>(n);
    k_sort<<<1, 1024, CAP * 8>>>();
    k_gather<<<(KSEL + 255) / 256, 256>>>(preds);
    k_nms<<<1, 1024, 173248>>>(out);
}

// round 2
// speedup vs baseline: 4.5745x; 4.5745x over previous
#include <cuda_runtime.h>

#define NA      102000
#define NFEAT   85
#define NC      80
#define KSEL    8192
#define CAP     16384
#define MAXDET  300
#define CONF    0.25f
#define IOUT    0.45f
#define MWORDS  256     // KSEL/32

// ---------------- device scratch ----------------
__device__ unsigned int       g_keys[NA];
__device__ unsigned char      g_cls[NA];
__device__ unsigned int       g_hist1[65536];
__device__ unsigned int       g_hist2[65536];
__device__ int                g_B;
__device__ unsigned int       g_A;
__device__ unsigned int       g_T;
__device__ unsigned int       g_cnt;
__device__ unsigned long long g_surv[CAP];
__device__ int                g_rank[CAP];
__device__ float4             g_top_box[KSEL];
__device__ float              g_top_area[KSEL];
__device__ float              g_top_score[KSEL];
__device__ float              g_top_cls[KSEL];
__device__ unsigned int       g_mask[KSEL * MWORDS];   // 8 MB suppression bitmask

// ---------------- 0: zero scratch (replay-idempotent) ----------------
__global__ void k_zero() {
    int i = blockIdx.x * blockDim.x + threadIdx.x;
    if (i < 65536) { g_hist1[i] = 0u; g_hist2[i] = 0u; }
    if (i < CAP)   g_rank[i] = 0;
    if (i < KSEL)  g_top_score[i] = 0.f;
    if (i == 0)    g_cnt = 0u;
}

// ---------------- 1: decode scores/classes, coarse histogram ----------------
__global__ void k_score(const float* __restrict__ preds, int n) {
    __shared__ float tile[128 * NFEAT];
    int base = blockIdx.x * 128;
    int cnt = n - base; if (cnt > 128) cnt = 128;
    if (cnt <= 0) return;
    int nel = cnt * NFEAT;
    const float* src = preds + (long long)base * NFEAT;
    for (int i = threadIdx.x; i < nel; i += 128) tile[i] = src[i];
    __syncthreads();
    int t = threadIdx.x;
    if (t < cnt) {
        const float* p = &tile[t * NFEAT];
        float obj = p[4];
        float best = -1.0f; int bi = 0;
        #pragma unroll 4
        for (int c = 0; c < NC; c++) {
            float v = __fmul_rn(p[5 + c], obj);
            if (v > best) { best = v; bi = c; }
        }
        float score = (obj > CONF) ? best : 0.0f;
        unsigned key = __float_as_uint(score);
        int a = base + t;
        g_keys[a] = key;
        g_cls[a]  = (unsigned char)bi;
        if (key) atomicAdd(&g_hist1[key >> 16], 1u);
    }
}

// ------- helper: 256-thread suffix-sum + select largest index with suf>=target -------
__device__ __forceinline__ int suffix_sel(unsigned* sA, unsigned* sB, int* sres,
                                          int tid, unsigned v, unsigned target) {
    sA[tid] = v; __syncthreads();
    unsigned* src = sA; unsigned* dst = sB;
    #pragma unroll
    for (int d = 1; d < 256; d <<= 1) {
        unsigned x = src[tid];
        if (tid + d < 256) x += src[tid + d];
        dst[tid] = x; __syncthreads();
        unsigned* tmp = src; src = dst; dst = tmp;
    }
    // 8 swaps -> suffix sums back in sA
    if (tid == 0) *sres = -1;
    __syncthreads();
    if (sA[tid] >= target) atomicMax(sres, tid);
    __syncthreads();
    return *sres;
}

// ---------------- 2: coarse threshold bucket (fully parallel) ----------------
__global__ void k_findB() {
    __shared__ unsigned sA[256], sB[256];
    __shared__ int sres;
    int tid = threadIdx.x;
    unsigned s = 0;
    const unsigned* h = g_hist1 + tid * 256;
    #pragma unroll 8
    for (int b = 0; b < 256; b++) s += h[b];
    int C = suffix_sel(sA, sB, &sres, tid, s, KSEL);
    if (C < 0) {            // fewer than KSEL positive scores
        if (tid == 0) { g_B = -1; g_A = sA[0]; }
        return;
    }
    unsigned A1 = (C < 255) ? sA[C + 1] : 0u;   // all threads read (pre-overwrite)
    __syncthreads();
    unsigned e = g_hist1[C * 256 + tid];
    int b = suffix_sel(sA, sB, &sres, tid, e, (unsigned)KSEL - A1);
    if (tid == 0) { g_B = C * 256 + b; g_A = A1 + ((b < 255) ? sA[b + 1] : 0u); }
}

// ---------------- 3: fine histogram within coarse bucket ----------------
__global__ void k_hist2(int n) {
    int a = blockIdx.x * blockDim.x + threadIdx.x;
    if (a < n) {
        int B = g_B;
        unsigned key = g_keys[a];
        if (B >= 0 && (int)(key >> 16) == B) atomicAdd(&g_hist2[key & 0xFFFFu], 1u);
    }
}

// ---------------- 4: exact fine threshold (fully parallel) ----------------
__global__ void k_findF() {
    __shared__ unsigned sA[256], sB[256];
    __shared__ int sres;
    int tid = threadIdx.x;
    int B = g_B;
    if (B < 0) { if (tid == 0) g_T = 1u; return; }
    unsigned target = (unsigned)KSEL - g_A;
    unsigned s = 0;
    const unsigned* h = g_hist2 + tid * 256;
    #pragma unroll 8
    for (int b = 0; b < 256; b++) s += h[b];
    int C = suffix_sel(sA, sB, &sres, tid, s, target);
    unsigned A1 = (C < 255) ? sA[C + 1] : 0u;
    __syncthreads();
    unsigned e = g_hist2[C * 256 + tid];
    int f = suffix_sel(sA, sB, &sres, tid, e, target - A1);
    if (tid == 0) {
        unsigned T = ((unsigned)B << 16) | (unsigned)(C * 256 + f);
        g_T = T ? T : 1u;
    }
}

// ---------------- 5: compact survivors (warp-aggregated atomics) ----------------
__global__ void k_compact(int n) {
    int a = blockIdx.x * blockDim.x + threadIdx.x;
    unsigned T = g_T;
    bool pred = false; unsigned key = 0;
    if (a < n) { key = g_keys[a]; pred = (key >= T); }
    unsigned m = __ballot_sync(0xffffffffu, pred);
    if (m) {
        int lane = threadIdx.x & 31;
        int leader = __ffs(m) - 1;
        unsigned base = 0;
        if (lane == leader) base = atomicAdd(&g_cnt, (unsigned)__popc(m));
        base = __shfl_sync(0xffffffffu, base, leader);
        if (pred) {
            unsigned pos = base + (unsigned)__popc(m & ((1u << lane) - 1u));
            if (pos < CAP)
                g_surv[pos] = ((unsigned long long)key << 32) | (unsigned)(~a);
        }
    }
}

// ---------------- 6: rank each survivor (all-pairs count, full-chip) ----------------
__global__ void __launch_bounds__(128) k_rank() {   // grid (CAP/128, CAP/1024)
    __shared__ unsigned long long sk[1024];
    unsigned cnt = g_cnt; if (cnt > CAP) cnt = CAP;
    int i0 = blockIdx.x * 128;
    int j0 = blockIdx.y * 1024;
    if (i0 >= (int)cnt || j0 >= (int)cnt) return;
    for (int t = threadIdx.x; t < 1024; t += 128) {
        int j = j0 + t;
        sk[t] = (j < (int)cnt) ? g_surv[j] : 0ULL;
    }
    __syncthreads();
    int i = i0 + threadIdx.x;
    if (i >= (int)cnt) return;
    unsigned long long key = g_surv[i];
    int c = 0;
    #pragma unroll 8
    for (int t = 0; t < 1024; t++) c += (sk[t] > key) ? 1 : 0;
    atomicAdd(&g_rank[i], c);
}

// ---------------- 7: scatter to sorted position + gather box/area/class ----------------
__global__ void k_scatter(const float* __restrict__ preds) {   // grid CAP/256
    int i = blockIdx.x * blockDim.x + threadIdx.x;
    unsigned cnt = g_cnt; if (cnt > CAP) cnt = CAP;
    if (i >= (int)cnt) return;
    int r = g_rank[i];
    if (r >= KSEL) return;
    unsigned long long key = g_surv[i];
    unsigned idx = ~(unsigned)(key & 0xFFFFFFFFu);
    float score = __uint_as_float((unsigned)(key >> 32));
    const float* p = preds + (size_t)idx * NFEAT;
    float x = p[0], y = p[1], w = p[2], h = p[3];
    float hh = __fmul_rn(h, 0.5f), hw = __fmul_rn(w, 0.5f);
    float4 box;
    box.x = __fsub_rn(y, hh);   // y1
    box.y = __fsub_rn(x, hw);   // x1
    box.z = __fadd_rn(y, hh);   // y2
    box.w = __fadd_rn(x, hw);   // x2
    float area = __fmul_rn(__fsub_rn(box.z, box.x), __fsub_rn(box.w, box.y));
    g_top_box[r]   = box;
    g_top_area[r]  = area;
    g_top_score[r] = score;
    g_top_cls[r]   = (float)g_cls[idx];
}

// ---------------- 8: build suppression bitmask (full-chip, upper triangle) ----------------
// Decision inter/(union+1e-9) > 0.45 taken via multiply with conservative band;
// exact __fdiv_rn only inside the band (rare) -> bit-exact vs reference.
__global__ void __launch_bounds__(256) k_mask() {   // grid (KSEL/32, KSEL/256)
    __shared__ float4 sjb[256]; __shared__ float sja[256];
    __shared__ float4 sib[32];  __shared__ float sia[32];
    int i0 = blockIdx.x * 32;
    int j0 = blockIdx.y * 256;
    if (j0 + 255 < i0) return;          // wholly below diagonal: bits stay 0
    int tid = threadIdx.x;
    if (tid < 32) { sib[tid] = g_top_box[i0 + tid]; sia[tid] = g_top_area[i0 + tid]; }
    sjb[tid] = g_top_box[j0 + tid];
    sja[tid] = g_top_area[j0 + tid];
    __syncthreads();
    int ri = tid >> 3, wj = tid & 7;
    int i = i0 + ri;
    float4 bi = sib[ri]; float ai = sia[ri];
    unsigned word = 0;
    int jb = wj * 32;
    #pragma unroll 4
    for (int b = 0; b < 32; b++) {
        float4 bj = sjb[jb + b];
        float ty = fmaxf(bi.x, bj.x);
        float tx = fmaxf(bi.y, bj.y);
        float byv = fminf(bi.z, bj.z);
        float bxv = fminf(bi.w, bj.w);
        float ih = fmaxf(__fsub_rn(byv, ty), 0.f);
        float iw = fmaxf(__fsub_rn(bxv, tx), 0.f);
        float inter = __fmul_rn(ih, iw);
        float uni = __fsub_rn(__fadd_rn(ai, sja[jb + b]), inter);
        float den = __fadd_rn(uni, 1e-9f);
        float m = __fmul_rn(IOUT, den);
        bool sup;
        if (inter > __fmul_rn(m, 1.00002f))      sup = true;
        else if (inter < __fmul_rn(m, 0.99998f)) sup = false;
        else sup = (__fdiv_rn(inter, den) > IOUT);   // rare exact path
        int j = j0 + jb + b;
        if (sup && j > i) word |= (1u << b);
    }
    g_mask[i * MWORDS + (j0 >> 5) + wj] = word;
}

// ---------------- 9: greedy scan over bitmask rows + write output ----------------
__global__ void k_scan(float* __restrict__ out) {   // 1 block, 256 threads
    __shared__ unsigned sup[MWORDS];
    __shared__ int kept[MAXDET];
    __shared__ int s_i, s_kept, s_cur;
    int tid = threadIdx.x;
    // init: invalid (score<=0) entries pre-suppressed
    {
        unsigned w = 0;
        int base = tid * 32;
        #pragma unroll 4
        for (int b = 0; b < 32; b++)
            if (!(g_top_score[base + b] > 0.f)) w |= (1u << b);
        sup[tid] = w;
    }
    if (tid == 0) { s_kept = 0; s_cur = 0; s_i = -1; }
    __syncthreads();
    for (;;) {
        if (tid < 32) {
            int curv = s_cur;
            int cw = curv >> 5;
            int found = -1;
            for (int w0 = cw; w0 < MWORDS; w0 += 32) {
                int wi = w0 + tid;
                unsigned live = 0;
                if (wi < MWORDS) {
                    live = ~sup[wi];
                    if (wi == cw) live &= (0xFFFFFFFFu << (curv & 31));
                }
                unsigned bal = __ballot_sync(0xffffffffu, live != 0u);
                if (bal) {
                    int l = __ffs(bal) - 1;
                    unsigned lw = __shfl_sync(0xffffffffu, live, l);
                    found = ((w0 + l) << 5) + __ffs(lw) - 1;
                    break;
                }
            }
            if (tid == 0) {
                if (found >= 0 && s_kept < MAXDET) {
                    kept[s_kept] = found; s_kept = s_kept + 1;
                    s_cur = found + 1; s_i = found;
                } else s_i = -1;
            }
        }
        __syncthreads();
        int i = s_i;
        if (i < 0) break;
        sup[tid] |= g_mask[i * MWORDS + tid];
        __syncthreads();
    }
    // outputs: boxes [0,1200) | classes [1200,1500) | scores [1500,1800)
    int m = s_kept;
    for (int t = tid; t < MAXDET; t += 256) {
        float4 b = make_float4(0.f, 0.f, 0.f, 0.f);
        float c = 0.f, s = 0.f;
        if (t < m) {
            int ki = kept[t];
            b = g_top_box[ki];
            c = g_top_cls[ki];
            s = g_top_score[ki];
        }
        out[4 * t + 0] = b.x; out[4 * t + 1] = b.y;
        out[4 * t + 2] = b.z; out[4 * t + 3] = b.w;
        out[1200 + t] = c;
        out[1500 + t] = s;
    }
}

// ---------------- launch ----------------
extern "C" void kernel_launch(void* const* d_in, const int* in_sizes, int n_in,
                              void* d_out, int out_size) {
    const float* preds = (const float*)d_in[0];
    float* out = (float*)d_out;
    int n = in_sizes[0] / NFEAT;
    if (n > NA) n = NA;

    k_zero   <<<256, 256>>>();
    k_score  <<<(n + 127) / 128, 128>>>(preds, n);
    k_findB  <<<1, 256>>>();
    k_hist2  <<<(n + 255) / 256, 256>>>(n);
    k_findF  <<<1, 256>>>();
    k_compact<<<(n + 255) / 256, 256>>>(n);
    k_rank   <<<dim3(CAP / 128, CAP / 1024), 128>>>();
    k_scatter<<<CAP / 256, 256>>>(preds);
    k_mask   <<<dim3(KSEL / 32, KSEL / 256), 256>>>();
    k_scan   <<<1, 256>>>(out);
}

// round 4
// speedup vs baseline: 6.8158x; 1.4899x over previous
#include <cuda_runtime.h>

#define NA      102000
#define NFEAT   85
#define NC      80
#define KSEL    8192
#define CAP     16384
#define MAXDET  300
#define CONF    0.25f
#define IOUT    0.45f
#define MWORDS  256     // KSEL/32
#define NBLK    8       // KSEL/1024

// ---------------- device scratch ----------------
__device__ unsigned int       g_keys[NA];
__device__ unsigned char      g_cls[NA];
__device__ unsigned int       g_hist1[65536];
__device__ unsigned int       g_hist2[65536];
__device__ int                g_B;
__device__ unsigned int       g_A;
__device__ unsigned int       g_T;
__device__ unsigned int       g_cnt;
__device__ unsigned long long g_surv[CAP];
__device__ int                g_rank[CAP];
__device__ float4             g_top_box[KSEL];
__device__ float              g_top_area[KSEL];
__device__ float              g_top_score[KSEL];
__device__ float              g_top_cls[KSEL];
__device__ unsigned int       g_mask[KSEL * MWORDS];   // 8 MB suppression bitmask

// ---------------- 0: zero scratch (replay-idempotent) ----------------
__global__ void k_zero() {
    int i = blockIdx.x * blockDim.x + threadIdx.x;
    if (i < 65536) { g_hist1[i] = 0u; g_hist2[i] = 0u; }
    if (i < CAP)   g_rank[i] = 0;
    if (i < KSEL)  g_top_score[i] = 0.f;
    if (i == 0)    g_cnt = 0u;
}

// ---------------- 1: decode scores/classes, coarse histogram ----------------
__global__ void k_score(const float* __restrict__ preds, int n) {
    __shared__ float tile[128 * NFEAT];
    int base = blockIdx.x * 128;
    int cnt = n - base; if (cnt > 128) cnt = 128;
    if (cnt <= 0) return;
    int nel = cnt * NFEAT;
    const float* src = preds + (long long)base * NFEAT;
    for (int i = threadIdx.x; i < nel; i += 128) tile[i] = src[i];
    __syncthreads();
    int t = threadIdx.x;
    if (t < cnt) {
        const float* p = &tile[t * NFEAT];
        float obj = p[4];
        float best = -1.0f; int bi = 0;
        #pragma unroll 4
        for (int c = 0; c < NC; c++) {
            float v = __fmul_rn(p[5 + c], obj);
            if (v > best) { best = v; bi = c; }
        }
        float score = (obj > CONF) ? best : 0.0f;
        unsigned key = __float_as_uint(score);
        int a = base + t;
        g_keys[a] = key;
        g_cls[a]  = (unsigned char)bi;
        if (key) atomicAdd(&g_hist1[key >> 16], 1u);
    }
}

// ------- helper: 256-thread suffix-sum + select largest index with suf>=target -------
__device__ __forceinline__ int suffix_sel(unsigned* sA, unsigned* sB, int* sres,
                                          int tid, unsigned v, unsigned target) {
    sA[tid] = v; __syncthreads();
    unsigned* src = sA; unsigned* dst = sB;
    #pragma unroll
    for (int d = 1; d < 256; d <<= 1) {
        unsigned x = src[tid];
        if (tid + d < 256) x += src[tid + d];
        dst[tid] = x; __syncthreads();
        unsigned* tmp = src; src = dst; dst = tmp;
    }
    if (tid == 0) *sres = -1;
    __syncthreads();
    if (sA[tid] >= target) atomicMax(sres, tid);
    __syncthreads();
    return *sres;
}

// ---------------- 2: coarse threshold bucket ----------------
__global__ void k_findB() {
    __shared__ unsigned sA[256], sB[256];
    __shared__ int sres;
    int tid = threadIdx.x;
    unsigned s = 0;
    const unsigned* h = g_hist1 + tid * 256;
    #pragma unroll 8
    for (int b = 0; b < 256; b++) s += h[b];
    int C = suffix_sel(sA, sB, &sres, tid, s, KSEL);
    if (C < 0) {
        if (tid == 0) { g_B = -1; g_A = sA[0]; }
        return;
    }
    unsigned A1 = (C < 255) ? sA[C + 1] : 0u;
    __syncthreads();
    unsigned e = g_hist1[C * 256 + tid];
    int b = suffix_sel(sA, sB, &sres, tid, e, (unsigned)KSEL - A1);
    if (tid == 0) { g_B = C * 256 + b; g_A = A1 + ((b < 255) ? sA[b + 1] : 0u); }
}

// ---------------- 3: fine histogram within coarse bucket ----------------
__global__ void k_hist2(int n) {
    int a = blockIdx.x * blockDim.x + threadIdx.x;
    if (a < n) {
        int B = g_B;
        unsigned key = g_keys[a];
        if (B >= 0 && (int)(key >> 16) == B) atomicAdd(&g_hist2[key & 0xFFFFu], 1u);
    }
}

// ---------------- 4: exact fine threshold ----------------
__global__ void k_findF() {
    __shared__ unsigned sA[256], sB[256];
    __shared__ int sres;
    int tid = threadIdx.x;
    int B = g_B;
    if (B < 0) { if (tid == 0) g_T = 1u; return; }
    unsigned target = (unsigned)KSEL - g_A;
    unsigned s = 0;
    const unsigned* h = g_hist2 + tid * 256;
    #pragma unroll 8
    for (int b = 0; b < 256; b++) s += h[b];
    int C = suffix_sel(sA, sB, &sres, tid, s, target);
    unsigned A1 = (C < 255) ? sA[C + 1] : 0u;
    __syncthreads();
    unsigned e = g_hist2[C * 256 + tid];
    int f = suffix_sel(sA, sB, &sres, tid, e, target - A1);
    if (tid == 0) {
        unsigned T = ((unsigned)B << 16) | (unsigned)(C * 256 + f);
        g_T = T ? T : 1u;
    }
}

// ---------------- 5: compact survivors ----------------
__global__ void k_compact(int n) {
    int a = blockIdx.x * blockDim.x + threadIdx.x;
    unsigned T = g_T;
    bool pred = false; unsigned key = 0;
    if (a < n) { key = g_keys[a]; pred = (key >= T); }
    unsigned m = __ballot_sync(0xffffffffu, pred);
    if (m) {
        int lane = threadIdx.x & 31;
        int leader = __ffs(m) - 1;
        unsigned base = 0;
        if (lane == leader) base = atomicAdd(&g_cnt, (unsigned)__popc(m));
        base = __shfl_sync(0xffffffffu, base, leader);
        if (pred) {
            unsigned pos = base + (unsigned)__popc(m & ((1u << lane) - 1u));
            if (pos < CAP)
                g_surv[pos] = ((unsigned long long)key << 32) | (unsigned)(~a);
        }
    }
}

// ---------------- 6: rank each survivor (all-pairs count) ----------------
__global__ void __launch_bounds__(128) k_rank() {   // grid (CAP/128, CAP/1024)
    __shared__ unsigned long long sk[1024];
    unsigned cnt = g_cnt; if (cnt > CAP) cnt = CAP;
    int i0 = blockIdx.x * 128;
    int j0 = blockIdx.y * 1024;
    if (i0 >= (int)cnt || j0 >= (int)cnt) return;
    for (int t = threadIdx.x; t < 1024; t += 128) {
        int j = j0 + t;
        sk[t] = (j < (int)cnt) ? g_surv[j] : 0ULL;
    }
    __syncthreads();
    int i = i0 + threadIdx.x;
    if (i >= (int)cnt) return;
    unsigned long long key = g_surv[i];
    int c = 0;
    #pragma unroll 8
    for (int t = 0; t < 1024; t++) c += (sk[t] > key) ? 1 : 0;
    atomicAdd(&g_rank[i], c);
}

// ---------------- 7: scatter to rank + gather box/area/class ----------------
__global__ void k_scatter(const float* __restrict__ preds) {
    int i = blockIdx.x * blockDim.x + threadIdx.x;
    unsigned cnt = g_cnt; if (cnt > CAP) cnt = CAP;
    if (i >= (int)cnt) return;
    int r = g_rank[i];
    if (r >= KSEL) return;
    unsigned long long key = g_surv[i];
    unsigned idx = ~(unsigned)(key & 0xFFFFFFFFu);
    float score = __uint_as_float((unsigned)(key >> 32));
    const float* p = preds + (size_t)idx * NFEAT;
    float x = p[0], y = p[1], w = p[2], h = p[3];
    float hh = __fmul_rn(h, 0.5f), hw = __fmul_rn(w, 0.5f);
    float4 box;
    box.x = __fsub_rn(y, hh);
    box.y = __fsub_rn(x, hw);
    box.z = __fadd_rn(y, hh);
    box.w = __fadd_rn(x, hw);
    float area = __fmul_rn(__fsub_rn(box.z, box.x), __fsub_rn(box.w, box.y));
    g_top_box[r]   = box;
    g_top_area[r]  = area;
    g_top_score[r] = score;
    g_top_cls[r]   = (float)g_cls[idx];
}

// ---------------- 8: suppression bitmask, branchless exact IoU ----------------
__global__ void __launch_bounds__(256) k_mask() {   // grid (KSEL/32, KSEL/256)
    __shared__ float4 sjb[256]; __shared__ float sja[256];
    __shared__ float4 sib[32];  __shared__ float sia[32];
    int i0 = blockIdx.x * 32;
    int j0 = blockIdx.y * 256;
    if (j0 + 255 < i0) return;          // wholly below diagonal: never read
    int tid = threadIdx.x;
    if (tid < 32) { sib[tid] = g_top_box[i0 + tid]; sia[tid] = g_top_area[i0 + tid]; }
    sjb[tid] = g_top_box[j0 + tid];
    sja[tid] = g_top_area[j0 + tid];
    __syncthreads();
    int ri = tid >> 3, wj = tid & 7;
    int i = i0 + ri;
    float4 bi = sib[ri]; float ai = sia[ri];
    unsigned word = 0;
    int jb = wj * 32;
    #pragma unroll 8
    for (int b = 0; b < 32; b++) {
        float4 bj = sjb[jb + b];
        float ty = fmaxf(bi.x, bj.x);
        float tx = fmaxf(bi.y, bj.y);
        float byv = fminf(bi.z, bj.z);
        float bxv = fminf(bi.w, bj.w);
        float ih = fmaxf(__fsub_rn(byv, ty), 0.f);
        float iw = fmaxf(__fsub_rn(bxv, tx), 0.f);
        float inter = __fmul_rn(ih, iw);
        float uni = __fsub_rn(__fadd_rn(ai, sja[jb + b]), inter);
        float den = __fadd_rn(uni, 1e-9f);
        bool sup = (__fdiv_rn(inter, den) > IOUT);   // exact, branchless
        int j = j0 + jb + b;
        word |= (sup && j > i) ? (1u << b) : 0u;
    }
    g_mask[(size_t)i * MWORDS + (j0 >> 5) + wj] = word;
}

// ---------------- 9: hierarchical greedy scan (smem mask block, register bitmap) ----------------
__global__ void __launch_bounds__(1024) k_scan(float* __restrict__ out) {
    extern __shared__ unsigned sm[];            // 32768 words = 128 KB
    __shared__ int kept[MAXDET];
    __shared__ unsigned blocksup[32];
    __shared__ int s_kept, s_skip;
    int tid = threadIdx.x;
    int warp = tid >> 5, lane = tid & 31;
    if (tid == 0) s_kept = 0;
    __syncthreads();

    for (int b = 0; b < NBLK; b++) {
        if (s_kept >= MAXDET) break;
        // (a) starting suppression words for this block: invalid scores + kept rows so far
        {
            float s = g_top_score[b * 1024 + warp * 32 + lane];
            unsigned inval = __ballot_sync(0xffffffffu, !(s > 0.f));
            unsigned v = 0;
            int nk = s_kept;
            for (int k = lane; k < nk; k += 32)
                v |= g_mask[(size_t)kept[k] * MWORDS + b * 32 + warp];
            v = __reduce_or_sync(0xffffffffu, v) | inval;
            if (lane == 0) blocksup[warp] = v;
        }
        __syncthreads();
        if (tid < 32) {
            unsigned v = blocksup[lane];
            unsigned full = __ballot_sync(0xffffffffu, v == 0xFFFFFFFFu);
            if (lane == 0) s_skip = (full == 0xFFFFFFFFu) ? 1 : 0;
        }
        __syncthreads();
        if (s_skip) continue;
        // (b) bulk-load the 1024x1024-bit diagonal sub-block into smem (uint4)
        for (int u = tid; u < 8192; u += 1024) {
            int i = u >> 3, w4 = u & 7;
            ((uint4*)sm)[u] =
                ((const uint4*)(g_mask + (size_t)(b * 1024 + i) * MWORDS + b * 32))[w4];
        }
        __syncthreads();
        // (c) warp-0 greedy: live bitmap in registers, mask rows from smem
        if (tid < 32) {
            unsigned sup_w = blocksup[lane];
            int cnt = s_kept;
            while (cnt < MAXDET) {
                unsigned live = ~sup_w;
                unsigned bal = __ballot_sync(0xffffffffu, live != 0u);
                if (!bal) break;
                int l = __ffs(bal) - 1;
                unsigned lw = __shfl_sync(0xffffffffu, live, l);
                int li = (l << 5) + __ffs(lw) - 1;
                if (lane == 0) kept[cnt] = b * 1024 + li;
                cnt++;
                sup_w |= sm[li * 32 + lane];               // conflict-free row OR
                if (lane == l) sup_w |= (1u << (li & 31)); // mark processed
            }
            if (lane == 0) s_kept = cnt;
        }
        __syncthreads();
    }
    // output: boxes [0,1200) | classes [1200,1500) | scores [1500,1800)
    int m = s_kept;
    for (int t = tid; t < MAXDET; t += 1024) {
        float4 bx = make_float4(0.f, 0.f, 0.f, 0.f);
        float c = 0.f, s = 0.f;
        if (t < m) {
            int ki = kept[t];
            bx = g_top_box[ki];
            c = g_top_cls[ki];
            s = g_top_score[ki];
        }
        out[4 * t + 0] = bx.x; out[4 * t + 1] = bx.y;
        out[4 * t + 2] = bx.z; out[4 * t + 3] = bx.w;
        out[1200 + t] = c;
        out[1500 + t] = s;
    }
}

// ---------------- launch ----------------
extern "C" void kernel_launch(void* const* d_in, const int* in_sizes, int n_in,
                              void* d_out, int out_size) {
    const float* preds = (const float*)d_in[0];
    float* out = (float*)d_out;
    int n = in_sizes[0] / NFEAT;
    if (n > NA) n = NA;

    cudaFuncSetAttribute(k_scan, cudaFuncAttributeMaxDynamicSharedMemorySize, 131072);

    k_zero   <<<256, 256>>>();
    k_score  <<<(n + 127) / 128, 128>>>(preds, n);
    k_findB  <<<1, 256>>>();
    k_hist2  <<<(n + 255) / 256, 256>>>(n);
    k_findF  <<<1, 256>>>();
    k_compact<<<(n + 255) / 256, 256>>>(n);
    k_rank   <<<dim3(CAP / 128, CAP / 1024), 128>>>();
    k_scatter<<<CAP / 256, 256>>>(preds);
    k_mask   <<<dim3(KSEL / 32, KSEL / 256), 256>>>();
    k_scan   <<<1, 1024, 131072>>>(out);
}